// round 3
// baseline (speedup 1.0000x reference)
#include <cuda_runtime.h>

#define BATCH 256
#define FEAT  512
#define NT    128   // threads/block; FEAT/4 float4s per row == NT

// Scratch + barrier state (allocation-free rule: __device__ globals).
// g_release is a monotone epoch -> safe across CUDA-graph replays with no reset node.
__device__ float    g_dist[BATCH];
__device__ unsigned g_arrive = 0;
__device__ volatile unsigned g_release = 0;

__global__ void __launch_bounds__(NT) cl_fused_kernel(
    const float* __restrict__ feats,
    const float* __restrict__ centers,
    const int*   __restrict__ labels,
    float*       __restrict__ out)
{
    const int b    = blockIdx.x;
    const int t    = threadIdx.x;
    const int warp = t >> 5;
    const int lane = t & 31;

    const float4* f4 = reinterpret_cast<const float4*>(feats) + (size_t)b * (FEAT / 4);
    const long long lab = labels[b];
    const float4* c4 = reinterpret_cast<const float4*>(centers) + (long long)lab * (FEAT / 4);

    float4 f = f4[t];
    float4 c = c4[t];

    float d0 = f.x - c.x, d1 = f.y - c.y, d2 = f.z - c.z, d3 = f.w - c.w;
    float dist = d0 * d0 + d1 * d1 + d2 * d2 + d3 * d3;
    float mx   = fmaxf(fmaxf(f.x, f.y), fmaxf(f.z, f.w));

    // ---- warp-level max reduce, then 4-warp combine (deterministic) ----
    #pragma unroll
    for (int o = 16; o > 0; o >>= 1)
        mx = fmaxf(mx, __shfl_xor_sync(0xffffffffu, mx, o));

    __shared__ float s_mx[4], s_d[4], s_e[4];
    if (lane == 0) s_mx[warp] = mx;
    __syncthreads();
    const float rowmax = fmaxf(fmaxf(s_mx[0], s_mx[1]), fmaxf(s_mx[2], s_mx[3]));

    float e = __expf(f.x - rowmax) + __expf(f.y - rowmax)
            + __expf(f.z - rowmax) + __expf(f.w - rowmax);

    // ---- warp-level sum reduce (dist & expsum), fixed shuffle tree ----
    #pragma unroll
    for (int o = 16; o > 0; o >>= 1) {
        dist += __shfl_xor_sync(0xffffffffu, dist, o);
        e    += __shfl_xor_sync(0xffffffffu, e, o);
    }
    if (lane == 0) { s_d[warp] = dist; s_e[warp] = e; }
    __syncthreads();

    const float blk_dist = (s_d[0] + s_d[1]) + (s_d[2] + s_d[3]);   // fixed order
    const float lse = rowmax + __logf((s_e[0] + s_e[1]) + (s_e[2] + s_e[3]));

    // ---- grid barrier: publish dist, arrive, release by epoch bump ----
    if (t == 0) {
        g_dist[b] = blk_dist;
        __threadfence();
        const unsigned e0 = g_release;              // sampled before arrival:
        const unsigned my = atomicAdd(&g_arrive, 1u); // bump can't precede our arrive
        if (my == BATCH - 1) {
            g_arrive = 0;                           // no concurrent arrivers remain
            __threadfence();
            g_release = e0 + 1;                     // release everyone
        } else {
            while (g_release == e0) { __nanosleep(64); }
        }
        __threadfence();                            // acquire: make g_dist[] visible
    }
    __syncthreads();

    // ---- deterministic total over 256 dists (L2-coherent loads) ----
    __shared__ float s_t[NT];
    s_t[t] = __ldcg(&g_dist[t]) + __ldcg(&g_dist[t + NT]);
    __syncthreads();
    #pragma unroll
    for (int s = NT / 2; s > 0; s >>= 1) {
        if (t < s) s_t[t] += s_t[t + s];
        __syncthreads();
    }
    const float add = s_t[0] - lse;

    // ---- epilogue straight from registers (feats never re-read) ----
    float4 o;
    o.x = f.x + add; o.y = f.y + add; o.z = f.z + add; o.w = f.w + add;
    reinterpret_cast<float4*>(out)[(size_t)b * (FEAT / 4) + t] = o;
}

extern "C" void kernel_launch(void* const* d_in, const int* in_sizes, int n_in,
                              void* d_out, int out_size)
{
    const float* feats   = (const float*)d_in[0];
    const float* centers = (const float*)d_in[1];
    const int*   labels  = (const int*)d_in[2];
    float* out = (float*)d_out;

    cl_fused_kernel<<<BATCH, NT>>>(feats, centers, labels, out);
}

// round 4
// speedup vs baseline: 1.0323x; 1.0323x over previous
#include <cuda_runtime.h>

#define BATCH 256
#define FEAT  512
#define NB    64          // blocks
#define NT    512         // threads/block; 4 rows per block, 128 threads per row
#define ROWS_PER_BLK 4

// Scratch + barrier state (allocation-free rule: __device__ globals).
// g_release is a monotone epoch -> safe across CUDA-graph replays, no reset node.
__device__ float    g_part[NB];        // per-block partial sum of 4 row dists
__device__ unsigned g_arrive = 0;
__device__ volatile unsigned g_release = 0;

__global__ void __launch_bounds__(NT) cl_fused_kernel(
    const float* __restrict__ feats,
    const float* __restrict__ centers,
    const int*   __restrict__ labels,
    float*       __restrict__ out)
{
    const int t    = threadIdx.x;
    const int warp = t >> 5;           // 0..15
    const int lane = t & 31;
    const int rg   = warp >> 2;        // row group within block: 0..3
    const int b    = blockIdx.x * ROWS_PER_BLK + rg;   // global batch row
    const int l    = t & 127;          // lane within the 128-thread row group

    const float4* f4 = reinterpret_cast<const float4*>(feats) + (size_t)b * (FEAT / 4);
    const long long lab = labels[b];
    const float4* c4 = reinterpret_cast<const float4*>(centers) + (long long)lab * (FEAT / 4);

    float4 f = f4[l];
    float4 c = c4[l];

    float d0 = f.x - c.x, d1 = f.y - c.y, d2 = f.z - c.z, d3 = f.w - c.w;
    float dist = d0 * d0 + d1 * d1 + d2 * d2 + d3 * d3;
    float mx   = fmaxf(fmaxf(f.x, f.y), fmaxf(f.z, f.w));

    // ---- phase 1: warp-reduce dist & max (fixed xor tree, no BAR) ----
    #pragma unroll
    for (int o = 16; o > 0; o >>= 1) {
        dist += __shfl_xor_sync(0xffffffffu, dist, o);
        mx    = fmaxf(mx, __shfl_xor_sync(0xffffffffu, mx, o));
    }

    __shared__ float s_d[16], s_mx[16], s_e[16], s_total;
    if (lane == 0) { s_d[warp] = dist; s_mx[warp] = mx; }
    __syncthreads();   // BAR #1

    // ---- thread 0: publish block partial + arrive (barrier work starts NOW) ----
    unsigned e0 = 0;
    if (t == 0) {
        // fixed-order sum: per row (d0+d1)+(d2+d3), then rows in order
        float p = 0.f;
        #pragma unroll
        for (int r = 0; r < 4; r++)
            p += (s_d[4 * r + 0] + s_d[4 * r + 1]) + (s_d[4 * r + 2] + s_d[4 * r + 3]);
        g_part[blockIdx.x] = p;
        __threadfence();
        e0 = g_release;                                // sample epoch before arrival
        unsigned my = atomicAdd(&g_arrive, 1u);
        if (my == NB - 1) {
            g_arrive = 0;                              // no concurrent arrivers remain
            __threadfence();
            g_release = e0 + 1;                        // release everyone
        }
    }

    // ---- overlap: softmax math while other blocks arrive ----
    const float rowmax = fmaxf(fmaxf(s_mx[4 * rg + 0], s_mx[4 * rg + 1]),
                               fmaxf(s_mx[4 * rg + 2], s_mx[4 * rg + 3]));
    float e = __expf(f.x - rowmax) + __expf(f.y - rowmax)
            + __expf(f.z - rowmax) + __expf(f.w - rowmax);
    #pragma unroll
    for (int o = 16; o > 0; o >>= 1)
        e += __shfl_xor_sync(0xffffffffu, e, o);
    if (lane == 0) s_e[warp] = e;

    // ---- thread 0: wait for release (mostly already done by now) ----
    if (t == 0) {
        while (g_release == e0) { __nanosleep(32); }
        __threadfence();                               // acquire g_part[]
    }
    __syncthreads();   // BAR #2 (orders s_e AND gates everyone on the release)

    const float lse = rowmax + __logf((s_e[4 * rg + 0] + s_e[4 * rg + 1])
                                    + (s_e[4 * rg + 2] + s_e[4 * rg + 3]));

    // ---- warp 0: deterministic total over 64 partials (fixed tree) ----
    if (warp == 0) {
        float v = __ldcg(&g_part[lane]) + __ldcg(&g_part[lane + 32]);
        #pragma unroll
        for (int o = 16; o > 0; o >>= 1)
            v += __shfl_xor_sync(0xffffffffu, v, o);
        if (lane == 0) s_total = v;
    }
    __syncthreads();   // BAR #3

    const float add = s_total - lse;

    // ---- epilogue straight from registers (feats never re-read) ----
    float4 o;
    o.x = f.x + add; o.y = f.y + add; o.z = f.z + add; o.w = f.w + add;
    reinterpret_cast<float4*>(out)[(size_t)b * (FEAT / 4) + l] = o;
}

extern "C" void kernel_launch(void* const* d_in, const int* in_sizes, int n_in,
                              void* d_out, int out_size)
{
    const float* feats   = (const float*)d_in[0];
    const float* centers = (const float*)d_in[1];
    const int*   labels  = (const int*)d_in[2];
    float* out = (float*)d_out;

    cl_fused_kernel<<<NB, NT>>>(feats, centers, labels, out);
}